// round 3
// baseline (speedup 1.0000x reference)
#include <cuda_runtime.h>
#include <math.h>

#define NN 512
#define DD 512
#define LN_EPS 1e-5f

typedef unsigned long long ull;

// ---------------- f32x2 packed helpers ----------------
__device__ __forceinline__ ull pk(float lo, float hi) {
    ull r; asm("mov.b64 %0, {%1, %2};" : "=l"(r) : "f"(lo), "f"(hi)); return r;
}
__device__ __forceinline__ ull pkdup(float v) {
    ull r; asm("mov.b64 %0, {%1, %1};" : "=l"(r) : "f"(v)); return r;
}
__device__ __forceinline__ void upk(ull v, float& lo, float& hi) {
    asm("mov.b64 {%0, %1}, %2;" : "=f"(lo), "=f"(hi) : "l"(v));
}
__device__ __forceinline__ ull fma2(ull a, ull b, ull c) {
    ull r; asm("fma.rn.f32x2 %0, %1, %2, %3;" : "=l"(r) : "l"(a), "l"(b), "l"(c)); return r;
}
__device__ __forceinline__ ull add2(ull a, ull b) {
    ull r; asm("add.rn.f32x2 %0, %1, %2;" : "=l"(r) : "l"(a), "l"(b)); return r;
}
__device__ __forceinline__ ull mul2(ull a, ull b) {
    ull r; asm("mul.rn.f32x2 %0, %1, %2;" : "=l"(r) : "l"(a), "l"(b)); return r;
}
__device__ __forceinline__ float tanh_approx(float x) {
    float r; asm("tanh.approx.f32 %0, %1;" : "=f"(r) : "f"(x)); return r;
}

// Scratch (all L2-resident):
__device__ float g_LR[2 * NN * DD];   // left rows, then right rows (2 MB)
__device__ float g_C[NN * NN];        // cross dot L_i . R_j (1 MB, upper tiles)
__device__ float g_S[2 * NN];         // row sums (L then R)
__device__ float g_Q[2 * NN];         // row sumsq
__device__ float g_A[2 * NN];         // dot(w*gamma, row)
__device__ float g_K[2];              // K1 = sum w*gamma, K2 = sum w*beta

// ---------------------------------------------------------------------------
// GEMM: left = E @ W1[:D],  right = E @ W1[D:] + b1   (z = 0 / 1)
// ---------------------------------------------------------------------------
#define BM 64
#define BN 64
#define BK 16

__global__ __launch_bounds__(256) void gemm_kernel(
    const float* __restrict__ E, const float* __restrict__ W1,
    const float* __restrict__ b1)
{
    __shared__ float As[BK][BM + 4];
    __shared__ float Bs[BK][BN + 4];

    const int z = blockIdx.z;
    const float* W = W1 + z * DD * DD;
    float* out = g_LR + z * NN * DD;

    const int m0 = blockIdx.y * BM;
    const int n0 = blockIdx.x * BN;
    const int t = threadIdx.x;

    const int am = t >> 2, ak = (t & 3) << 2;
    const int bk = t >> 4, bn = (t & 15) << 2;
    const int ty = t >> 4, tx = t & 15;

    ull acc[4][2];
#pragma unroll
    for (int i = 0; i < 4; i++) { acc[i][0] = 0ull; acc[i][1] = 0ull; }

    for (int k0 = 0; k0 < DD; k0 += BK) {
        float4 av = *(const float4*)&E[(m0 + am) * DD + k0 + ak];
        As[ak + 0][am] = av.x;
        As[ak + 1][am] = av.y;
        As[ak + 2][am] = av.z;
        As[ak + 3][am] = av.w;
        *(float4*)&Bs[bk][bn] = *(const float4*)&W[(k0 + bk) * DD + n0 + bn];
        __syncthreads();
#pragma unroll
        for (int k = 0; k < BK; k++) {
            float4 a = *(const float4*)&As[k][ty << 2];
            float4 b = *(const float4*)&Bs[k][tx << 2];
            ull b01 = pk(b.x, b.y);
            ull b23 = pk(b.z, b.w);
            ull a0 = pkdup(a.x), a1 = pkdup(a.y), a2 = pkdup(a.z), a3 = pkdup(a.w);
            acc[0][0] = fma2(a0, b01, acc[0][0]);
            acc[0][1] = fma2(a0, b23, acc[0][1]);
            acc[1][0] = fma2(a1, b01, acc[1][0]);
            acc[1][1] = fma2(a1, b23, acc[1][1]);
            acc[2][0] = fma2(a2, b01, acc[2][0]);
            acc[2][1] = fma2(a2, b23, acc[2][1]);
            acc[3][0] = fma2(a3, b01, acc[3][0]);
            acc[3][1] = fma2(a3, b23, acc[3][1]);
        }
        __syncthreads();
    }

#pragma unroll
    for (int i = 0; i < 4; i++) {
        int row = m0 + (ty << 2) + i;
        int col = n0 + (tx << 2);
        float4 r;
        upk(acc[i][0], r.x, r.y);
        upk(acc[i][1], r.z, r.w);
        if (z) {
            r.x += b1[col + 0];
            r.y += b1[col + 1];
            r.z += b1[col + 2];
            r.w += b1[col + 3];
        }
        *(float4*)&out[row * DD + col] = r;
    }
}

// ---------------------------------------------------------------------------
// Cross GEMM: C = L @ R^T, only upper-triangular 64x64 tiles (bi <= bj).
// ---------------------------------------------------------------------------
__global__ __launch_bounds__(256) void cross_kernel()
{
    const int bi = blockIdx.y;   // i tile
    const int bj = blockIdx.x;   // j tile
    if (bi > bj) return;

    __shared__ float As[BK][BM + 4];
    __shared__ float Bs[BK][BN + 4];

    const float* L = g_LR;
    const float* R = g_LR + NN * DD;

    const int m0 = bi * BM;
    const int n0 = bj * BN;
    const int t = threadIdx.x;

    const int am = t >> 2, ak = (t & 3) << 2;   // also used for B (transposed load)
    const int ty = t >> 4, tx = t & 15;

    ull acc[4][2];
#pragma unroll
    for (int i = 0; i < 4; i++) { acc[i][0] = 0ull; acc[i][1] = 0ull; }

    for (int k0 = 0; k0 < DD; k0 += BK) {
        float4 av = *(const float4*)&L[(m0 + am) * DD + k0 + ak];
        As[ak + 0][am] = av.x;
        As[ak + 1][am] = av.y;
        As[ak + 2][am] = av.z;
        As[ak + 3][am] = av.w;
        float4 bv = *(const float4*)&R[(n0 + am) * DD + k0 + ak];
        Bs[ak + 0][am] = bv.x;
        Bs[ak + 1][am] = bv.y;
        Bs[ak + 2][am] = bv.z;
        Bs[ak + 3][am] = bv.w;
        __syncthreads();
#pragma unroll
        for (int k = 0; k < BK; k++) {
            float4 a = *(const float4*)&As[k][ty << 2];
            float4 b = *(const float4*)&Bs[k][tx << 2];
            ull b01 = pk(b.x, b.y);
            ull b23 = pk(b.z, b.w);
            ull a0 = pkdup(a.x), a1 = pkdup(a.y), a2 = pkdup(a.z), a3 = pkdup(a.w);
            acc[0][0] = fma2(a0, b01, acc[0][0]);
            acc[0][1] = fma2(a0, b23, acc[0][1]);
            acc[1][0] = fma2(a1, b01, acc[1][0]);
            acc[1][1] = fma2(a1, b23, acc[1][1]);
            acc[2][0] = fma2(a2, b01, acc[2][0]);
            acc[2][1] = fma2(a2, b23, acc[2][1]);
            acc[3][0] = fma2(a3, b01, acc[3][0]);
            acc[3][1] = fma2(a3, b23, acc[3][1]);
        }
        __syncthreads();
    }

#pragma unroll
    for (int i = 0; i < 4; i++) {
        int row = m0 + (ty << 2) + i;
        int col = n0 + (tx << 2);
        float4 r;
        upk(acc[i][0], r.x, r.y);
        upk(acc[i][1], r.z, r.w);
        *(float4*)&g_C[row * NN + col] = r;
    }
}

// ---------------------------------------------------------------------------
// Row stats: S=sum, Q=sumsq, A=dot(w*gamma, row) for all 1024 rows of g_LR.
// Block 256 also computes K1 = sum w*g, K2 = sum w*beta.
// ---------------------------------------------------------------------------
__global__ __launch_bounds__(128) void rowstats_kernel(
    const float* __restrict__ gamma, const float* __restrict__ beta,
    const float* __restrict__ W2)
{
    const int t = threadIdx.x;
    const int lane = t & 31;
    const int w = t >> 5;

    if (blockIdx.x == 256) {
        if (w == 0) {
            float k1 = 0.f, k2 = 0.f;
#pragma unroll
            for (int c = 0; c < 16; c++) {
                int d = lane + (c << 5);
                float wv = W2[d];
                k1 = fmaf(wv, gamma[d], k1);
                k2 = fmaf(wv, beta[d], k2);
            }
#pragma unroll
            for (int o = 16; o > 0; o >>= 1) {
                k1 += __shfl_xor_sync(0xffffffffu, k1, o);
                k2 += __shfl_xor_sync(0xffffffffu, k2, o);
            }
            if (lane == 0) { g_K[0] = k1; g_K[1] = k2; }
        }
        return;
    }

    const int rid = blockIdx.x * 4 + w;       // 0..1023
    const float* row = g_LR + rid * DD;

    float s = 0.f, q = 0.f, a = 0.f;
#pragma unroll
    for (int c = 0; c < 4; c++) {
        int col = (lane + (c << 5)) << 2;
        float4 v = *(const float4*)&row[col];
        float4 gv = *(const float4*)&gamma[col];
        float4 wv = *(const float4*)&W2[col];
        s += v.x + v.y + v.z + v.w;
        q = fmaf(v.x, v.x, q); q = fmaf(v.y, v.y, q);
        q = fmaf(v.z, v.z, q); q = fmaf(v.w, v.w, q);
        a = fmaf(v.x, wv.x * gv.x, a); a = fmaf(v.y, wv.y * gv.y, a);
        a = fmaf(v.z, wv.z * gv.z, a); a = fmaf(v.w, wv.w * gv.w, a);
    }
#pragma unroll
    for (int o = 16; o > 0; o >>= 1) {
        s += __shfl_xor_sync(0xffffffffu, s, o);
        q += __shfl_xor_sync(0xffffffffu, q, o);
        a += __shfl_xor_sync(0xffffffffu, a, o);
    }
    if (lane == 0) { g_S[rid] = s; g_Q[rid] = q; g_A[rid] = a; }
}

// ---------------------------------------------------------------------------
// Pairwise kernel: single pass, no LN reductions (stats from decomposition),
// deferred output reductions.
// ---------------------------------------------------------------------------
#define TI 8
#define TT (NN / TI)   // 64; blocks = 2080

__global__ __launch_bounds__(256) void pair_kernel(
    const float* __restrict__ gamma, const float* __restrict__ beta,
    const float* __restrict__ W2, const float* __restrict__ b2,
    float* __restrict__ out)
{
    __shared__ float sl[TI][DD];
    __shared__ float sr[TI][DD];
    __shared__ float sSl[TI], sQl[TI], sAl[TI];
    __shared__ float sSr[TI], sQr[TI], sBr[TI];
    __shared__ float sC[TI][TI];
    __shared__ float sK[2];

    // Decode linear block id -> upper-triangular tile (ti <= tj).
    int bid = blockIdx.x;
    int ti = (int)((2.0f * TT + 1.0f -
                    sqrtf((2.0f * TT + 1.0f) * (2.0f * TT + 1.0f) - 8.0f * (float)bid)) * 0.5f);
    if (ti < 0) ti = 0;
    if (ti > TT - 1) ti = TT - 1;
    while (ti > 0 && (ti * TT - ((ti * (ti - 1)) >> 1)) > bid) ti--;
    while (((ti + 1) * TT - (((ti + 1) * ti) >> 1)) <= bid) ti++;
    const int tj = ti + bid - (ti * TT - ((ti * (ti - 1)) >> 1));

    const int t = threadIdx.x;
    const int lane = t & 31;
    const int w = t >> 5;

    const float* L = g_LR;
    const float* R = g_LR + NN * DD;

    // Stage rows.
#pragma unroll
    for (int c = 0; c < 4; c++) {
        int idx = c * 256 + t;
        int r = idx >> 7;
        int col = (idx & 127) << 2;
        *(float4*)&sl[r][col] = *(const float4*)&L[(ti * TI + r) * DD + col];
        *(float4*)&sr[r][col] = *(const float4*)&R[(tj * TI + r) * DD + col];
    }
    // Stage stats + C tile.
    if (t < 8)              sSl[t] = g_S[ti * TI + t];
    else if (t < 16)        sQl[t - 8]  = g_Q[ti * TI + t - 8];
    else if (t < 24)        sAl[t - 16] = g_A[ti * TI + t - 16];
    else if (t < 32)        sSr[t - 24] = g_S[NN + tj * TI + t - 24];
    else if (t < 40)        sQr[t - 32] = g_Q[NN + tj * TI + t - 32];
    else if (t < 48)        sBr[t - 40] = g_A[NN + tj * TI + t - 40];
    else if (t < 112) {
        int li = t - 48;
        sC[li >> 3][li & 7] = g_C[(ti * TI + (li >> 3)) * NN + tj * TI + (li & 7)];
    }
    else if (t == 112)      sK[0] = g_K[0];
    else if (t == 113)      sK[1] = g_K[1];

    // Packed per-lane parameters: pair k covers d = 64k + 2*lane.
    ull g2[8], be2[8], hw2[8];
#pragma unroll
    for (int k = 0; k < 8; k++) {
        int d = (k << 6) + (lane << 1);
        float2 gv = *(const float2*)&gamma[d];
        float2 bv = *(const float2*)&beta[d];
        float2 wv = *(const float2*)&W2[d];
        g2[k]  = pk(gv.x, gv.y);
        be2[k] = pk(bv.x, bv.y);
        hw2[k] = pk(0.5f * wv.x, 0.5f * wv.y);
    }
    const float b2v = b2[0];
    const ull C1 = pkdup(0.0356774081f);
    const ull C0 = pkdup(0.7978845608f);

    __syncthreads();

    const int i = ti * TI + w;
    const float Sl = sSl[w], Ql = sQl[w], Al = sAl[w];
    const float K1 = sK[0], K2 = sK[1];

    ull lrow[8];
#pragma unroll
    for (int k = 0; k < 8; k++)
        lrow[k] = *(const ull*)&sl[w][(k << 6) + (lane << 1)];

    float accJ[TI];

#pragma unroll
    for (int jj = 0; jj < TI; jj++) {
        // LN stats from decomposition (uniform scalars, no reduction).
        float sum = Sl + sSr[jj];
        float ssq = Ql + sQr[jj] + 2.0f * sC[w][jj];
        float mu  = sum * (1.0f / DD);
        float var = fmaf(-mu, mu, ssq * (1.0f / DD));
        float rstd = rsqrtf(var + LN_EPS);
        float cc = -mu * rstd;
        // Closed-form linear half of the GELU dot: 0.5 * sum(w * x)
        float lin = 0.5f * fmaf(rstd, Al + sBr[jj], fmaf(cc, K1, K2));

        ull rstd2 = pkdup(rstd);
        ull cc2 = pkdup(cc);

        ull accA = 0ull;
#pragma unroll
        for (int k = 0; k < 8; k++) {
            ull r2 = *(const ull*)&sr[jj][(k << 6) + (lane << 1)];
            ull v = add2(lrow[k], r2);
            ull x = fma2(v, rstd2, cc2);
            x = fma2(x, g2[k], be2[k]);
            ull x2 = mul2(x, x);
            ull p = fma2(x2, C1, C0);
            ull u = mul2(x, p);
            float ulo, uhi;
            upk(u, ulo, uhi);
            ull th = pk(tanh_approx(ulo), tanh_approx(uhi));
            ull xw = mul2(x, hw2[k]);
            accA = fma2(xw, th, accA);     // sum 0.5*w*x*tanh
        }
        float alo, ahi;
        upk(accA, alo, ahi);
        // lin/32 per lane sums to lin across the 32-lane reduction.
        accJ[jj] = (alo + ahi) + lin * 0.03125f;
    }

    // Deferred reductions: 8 independent shuffle trees.
#pragma unroll
    for (int jj = 0; jj < TI; jj++) {
        float v = accJ[jj];
#pragma unroll
        for (int o = 16; o > 0; o >>= 1)
            v += __shfl_xor_sync(0xffffffffu, v, o);
        accJ[jj] = v;
    }

#pragma unroll
    for (int jj = 0; jj < TI; jj++) {
        int j = tj * TI + jj;
        float zv = accJ[jj] + b2v;
        float e = __expf(-zv);
        float sig = __fdividef(1.0f, 1.0f + e);
        if (lane == jj && i <= j) {
            out[i * NN + j] = sig;
            out[j * NN + i] = sig;
        }
    }
}

// ---------------------------------------------------------------------------
extern "C" void kernel_launch(void* const* d_in, const int* in_sizes, int n_in,
                              void* d_out, int out_size)
{
    const float* E     = (const float*)d_in[0];
    const float* W1    = (const float*)d_in[1];
    const float* b1    = (const float*)d_in[2];
    const float* gamma = (const float*)d_in[3];
    const float* beta  = (const float*)d_in[4];
    const float* W2    = (const float*)d_in[5];
    const float* b2    = (const float*)d_in[6];
    float* out = (float*)d_out;

    dim3 ggrid(NN / BN, NN / BM, 2);
    gemm_kernel<<<ggrid, 256>>>(E, W1, b1);

    rowstats_kernel<<<257, 128>>>(gamma, beta, W2);

    dim3 cgrid(NN / BN, NN / BM);
    cross_kernel<<<cgrid, 256>>>();

    const int nblocks = TT * (TT + 1) / 2;   // 2080
    pair_kernel<<<nblocks, 256>>>(gamma, beta, W2, b2, out);
}

// round 4
// speedup vs baseline: 1.2151x; 1.2151x over previous
#include <cuda_runtime.h>
#include <math.h>
#include <stdint.h>

#define NN 512
#define DD 512
#define LN_EPS 1e-5f

typedef unsigned long long ull;

// ---------------- f32x2 packed helpers ----------------
__device__ __forceinline__ ull pk(float lo, float hi) {
    ull r; asm("mov.b64 %0, {%1, %2};" : "=l"(r) : "f"(lo), "f"(hi)); return r;
}
__device__ __forceinline__ ull pkdup(float v) {
    ull r; asm("mov.b64 %0, {%1, %1};" : "=l"(r) : "f"(v)); return r;
}
__device__ __forceinline__ void upk(ull v, float& lo, float& hi) {
    asm("mov.b64 {%0, %1}, %2;" : "=f"(lo), "=f"(hi) : "l"(v));
}
__device__ __forceinline__ ull fma2(ull a, ull b, ull c) {
    ull r; asm("fma.rn.f32x2 %0, %1, %2, %3;" : "=l"(r) : "l"(a), "l"(b), "l"(c)); return r;
}
__device__ __forceinline__ ull add2(ull a, ull b) {
    ull r; asm("add.rn.f32x2 %0, %1, %2;" : "=l"(r) : "l"(a), "l"(b)); return r;
}
__device__ __forceinline__ ull mul2(ull a, ull b) {
    ull r; asm("mul.rn.f32x2 %0, %1, %2;" : "=l"(r) : "l"(a), "l"(b)); return r;
}
__device__ __forceinline__ float tanh_approx(float x) {
    float r; asm("tanh.approx.f32 %0, %1;" : "=f"(r) : "f"(x)); return r;
}
__device__ __forceinline__ float to_tf32(float x) {
    float r; asm("cvt.rna.tf32.f32 %0, %1;" : "=f"(r) : "f"(x)); return r;
}
__device__ __forceinline__ void mma_tf32(float4& d,
    uint32_t a0, uint32_t a1, uint32_t a2, uint32_t a3,
    uint32_t b0, uint32_t b1)
{
    asm("mma.sync.aligned.m16n8k8.row.col.f32.tf32.tf32.f32 "
        "{%0,%1,%2,%3}, {%4,%5,%6,%7}, {%8,%9}, {%0,%1,%2,%3};"
        : "+f"(d.x), "+f"(d.y), "+f"(d.z), "+f"(d.w)
        : "r"(a0), "r"(a1), "r"(a2), "r"(a3), "r"(b0), "r"(b1));
}

// Scratch (all L2-resident):
__device__ float g_LR[2 * NN * DD];   // left rows, then right rows (2 MB)
__device__ float g_C[NN * NN];        // cross dot L_i . R_j (upper tiles)
__device__ float g_S[2 * NN];         // row sums (L then R)
__device__ float g_Q[2 * NN];         // row sumsq
__device__ float g_A[2 * NN];         // dot(w*gamma, row)
__device__ float g_K[2];              // K1 = sum w*gamma, K2 = sum w*beta

// ---------------------------------------------------------------------------
// Tensor-core GEMM: left = E @ W1[:D],  right = E @ W1[D:] + b1  (z = 0/1)
// 128 threads (4 warps), BM=BN=64, BK=32, warp tile 32x32, m16n8k8 tf32.
// ---------------------------------------------------------------------------
__global__ __launch_bounds__(128) void gemm_tc(
    const float* __restrict__ E, const float* __restrict__ W1,
    const float* __restrict__ b1)
{
    __shared__ float As[64][36];   // E tile, row-major [m][k]
    __shared__ float Bs[32][72];   // W tile, row-major [k][n]

    const int z = blockIdx.z;
    const float* W = W1 + z * DD * DD;
    float* out = g_LR + z * NN * DD;

    const int m0 = blockIdx.y * 64;
    const int n0 = blockIdx.x * 64;
    const int t = threadIdx.x;
    const int lane = t & 31;
    const int w = t >> 5;
    const int g = lane >> 2, tig = lane & 3;
    const int mrow0 = (w >> 1) * 32;
    const int ncol0 = (w & 1) * 32;

    float4 acc[2][4];
#pragma unroll
    for (int mt = 0; mt < 2; mt++)
#pragma unroll
        for (int nt = 0; nt < 4; nt++) acc[mt][nt] = make_float4(0.f, 0.f, 0.f, 0.f);

    for (int k0 = 0; k0 < DD; k0 += 32) {
#pragma unroll
        for (int j = 0; j < 4; j++) {
            int idx4 = t + j * 128;
            int ar = idx4 >> 3, ac = (idx4 & 7) << 2;
            float4 av = *(const float4*)&E[(m0 + ar) * DD + k0 + ac];
            av.x = to_tf32(av.x); av.y = to_tf32(av.y);
            av.z = to_tf32(av.z); av.w = to_tf32(av.w);
            *(float4*)&As[ar][ac] = av;
            int br = idx4 >> 4, bc = (idx4 & 15) << 2;
            float4 bv = *(const float4*)&W[(k0 + br) * DD + n0 + bc];
            bv.x = to_tf32(bv.x); bv.y = to_tf32(bv.y);
            bv.z = to_tf32(bv.z); bv.w = to_tf32(bv.w);
            *(float4*)&Bs[br][bc] = bv;
        }
        __syncthreads();
#pragma unroll
        for (int kk = 0; kk < 32; kk += 8) {
            uint32_t a[2][4];
#pragma unroll
            for (int mt = 0; mt < 2; mt++) {
                int base = mrow0 + mt * 16;
                a[mt][0] = __float_as_uint(As[base + g][kk + tig]);
                a[mt][1] = __float_as_uint(As[base + g + 8][kk + tig]);
                a[mt][2] = __float_as_uint(As[base + g][kk + tig + 4]);
                a[mt][3] = __float_as_uint(As[base + g + 8][kk + tig + 4]);
            }
            uint32_t b[4][2];
#pragma unroll
            for (int nt = 0; nt < 4; nt++) {
                int col = ncol0 + nt * 8 + g;
                b[nt][0] = __float_as_uint(Bs[kk + tig][col]);
                b[nt][1] = __float_as_uint(Bs[kk + tig + 4][col]);
            }
#pragma unroll
            for (int mt = 0; mt < 2; mt++)
#pragma unroll
                for (int nt = 0; nt < 4; nt++)
                    mma_tf32(acc[mt][nt], a[mt][0], a[mt][1], a[mt][2], a[mt][3],
                             b[nt][0], b[nt][1]);
        }
        __syncthreads();
    }

#pragma unroll
    for (int mt = 0; mt < 2; mt++) {
#pragma unroll
        for (int nt = 0; nt < 4; nt++) {
            int row = m0 + mrow0 + mt * 16 + g;
            int col = n0 + ncol0 + nt * 8 + 2 * tig;
            float2 lo = make_float2(acc[mt][nt].x, acc[mt][nt].y);
            float2 hi = make_float2(acc[mt][nt].z, acc[mt][nt].w);
            if (z) {
                float b0v = b1[col], b1v = b1[col + 1];
                lo.x += b0v; lo.y += b1v;
                hi.x += b0v; hi.y += b1v;
            }
            *(float2*)&out[row * DD + col] = lo;
            *(float2*)&out[(row + 8) * DD + col] = hi;
        }
    }
}

// ---------------------------------------------------------------------------
// Tensor-core cross GEMM: C = L @ R^T, upper-triangular 64x64 tiles only.
// B[k][n] = R[n][k]  ->  stage R rows like A and read transposed fragments.
// ---------------------------------------------------------------------------
__global__ __launch_bounds__(128) void cross_tc()
{
    __shared__ float As[64][36];   // L rows [m][k]
    __shared__ float Rs[64][36];   // R rows [n][k]

    // decode linear bid -> (bi <= bj), 36 blocks over 8x8 tiles
    int bid = blockIdx.x;
    int bi = 0, rem = bid;
    while (rem >= 8 - bi) { rem -= 8 - bi; bi++; }
    const int bj = bi + rem;

    const float* L = g_LR;
    const float* R = g_LR + NN * DD;

    const int m0 = bi * 64;
    const int n0 = bj * 64;
    const int t = threadIdx.x;
    const int lane = t & 31;
    const int w = t >> 5;
    const int g = lane >> 2, tig = lane & 3;
    const int mrow0 = (w >> 1) * 32;
    const int ncol0 = (w & 1) * 32;

    float4 acc[2][4];
#pragma unroll
    for (int mt = 0; mt < 2; mt++)
#pragma unroll
        for (int nt = 0; nt < 4; nt++) acc[mt][nt] = make_float4(0.f, 0.f, 0.f, 0.f);

    for (int k0 = 0; k0 < DD; k0 += 32) {
#pragma unroll
        for (int j = 0; j < 4; j++) {
            int idx4 = t + j * 128;
            int ar = idx4 >> 3, ac = (idx4 & 7) << 2;
            float4 av = *(const float4*)&L[(m0 + ar) * DD + k0 + ac];
            av.x = to_tf32(av.x); av.y = to_tf32(av.y);
            av.z = to_tf32(av.z); av.w = to_tf32(av.w);
            *(float4*)&As[ar][ac] = av;
            float4 rv = *(const float4*)&R[(n0 + ar) * DD + k0 + ac];
            rv.x = to_tf32(rv.x); rv.y = to_tf32(rv.y);
            rv.z = to_tf32(rv.z); rv.w = to_tf32(rv.w);
            *(float4*)&Rs[ar][ac] = rv;
        }
        __syncthreads();
#pragma unroll
        for (int kk = 0; kk < 32; kk += 8) {
            uint32_t a[2][4];
#pragma unroll
            for (int mt = 0; mt < 2; mt++) {
                int base = mrow0 + mt * 16;
                a[mt][0] = __float_as_uint(As[base + g][kk + tig]);
                a[mt][1] = __float_as_uint(As[base + g + 8][kk + tig]);
                a[mt][2] = __float_as_uint(As[base + g][kk + tig + 4]);
                a[mt][3] = __float_as_uint(As[base + g + 8][kk + tig + 4]);
            }
            uint32_t b[4][2];
#pragma unroll
            for (int nt = 0; nt < 4; nt++) {
                int nrow = ncol0 + nt * 8 + g;
                b[nt][0] = __float_as_uint(Rs[nrow][kk + tig]);
                b[nt][1] = __float_as_uint(Rs[nrow][kk + tig + 4]);
            }
#pragma unroll
            for (int mt = 0; mt < 2; mt++)
#pragma unroll
                for (int nt = 0; nt < 4; nt++)
                    mma_tf32(acc[mt][nt], a[mt][0], a[mt][1], a[mt][2], a[mt][3],
                             b[nt][0], b[nt][1]);
        }
        __syncthreads();
    }

#pragma unroll
    for (int mt = 0; mt < 2; mt++) {
#pragma unroll
        for (int nt = 0; nt < 4; nt++) {
            int row = m0 + mrow0 + mt * 16 + g;
            int col = n0 + ncol0 + nt * 8 + 2 * tig;
            *(float2*)&g_C[row * NN + col] =
                make_float2(acc[mt][nt].x, acc[mt][nt].y);
            *(float2*)&g_C[(row + 8) * NN + col] =
                make_float2(acc[mt][nt].z, acc[mt][nt].w);
        }
    }
}

// ---------------------------------------------------------------------------
// Row stats: S=sum, Q=sumsq, A=dot(w*gamma, row) for all 1024 rows of g_LR.
// Block 256 computes K1 = sum w*gamma, K2 = sum w*beta.
// ---------------------------------------------------------------------------
__global__ __launch_bounds__(128) void rowstats_kernel(
    const float* __restrict__ gamma, const float* __restrict__ beta,
    const float* __restrict__ W2)
{
    const int t = threadIdx.x;
    const int lane = t & 31;
    const int w = t >> 5;

    if (blockIdx.x == 256) {
        if (w == 0) {
            float k1 = 0.f, k2 = 0.f;
#pragma unroll
            for (int c = 0; c < 16; c++) {
                int d = lane + (c << 5);
                float wv = W2[d];
                k1 = fmaf(wv, gamma[d], k1);
                k2 = fmaf(wv, beta[d], k2);
            }
#pragma unroll
            for (int o = 16; o > 0; o >>= 1) {
                k1 += __shfl_xor_sync(0xffffffffu, k1, o);
                k2 += __shfl_xor_sync(0xffffffffu, k2, o);
            }
            if (lane == 0) { g_K[0] = k1; g_K[1] = k2; }
        }
        return;
    }

    const int rid = blockIdx.x * 4 + w;       // 0..1023
    const float* row = g_LR + rid * DD;

    float s = 0.f, q = 0.f, a = 0.f;
#pragma unroll
    for (int c = 0; c < 4; c++) {
        int col = (lane + (c << 5)) << 2;
        float4 v = *(const float4*)&row[col];
        float4 gv = *(const float4*)&gamma[col];
        float4 wv = *(const float4*)&W2[col];
        s += v.x + v.y + v.z + v.w;
        q = fmaf(v.x, v.x, q); q = fmaf(v.y, v.y, q);
        q = fmaf(v.z, v.z, q); q = fmaf(v.w, v.w, q);
        a = fmaf(v.x, wv.x * gv.x, a); a = fmaf(v.y, wv.y * gv.y, a);
        a = fmaf(v.z, wv.z * gv.z, a); a = fmaf(v.w, wv.w * gv.w, a);
    }
#pragma unroll
    for (int o = 16; o > 0; o >>= 1) {
        s += __shfl_xor_sync(0xffffffffu, s, o);
        q += __shfl_xor_sync(0xffffffffu, q, o);
        a += __shfl_xor_sync(0xffffffffu, a, o);
    }
    if (lane == 0) { g_S[rid] = s; g_Q[rid] = q; g_A[rid] = a; }
}

// ---------------------------------------------------------------------------
// Pairwise kernel: single pass, stats via decomposition, params in smem,
// k-outer / jj-inner loop order to amortize param loads.
// ---------------------------------------------------------------------------
#define TI 8
#define TT (NN / TI)   // 64; blocks = 2080

__global__ __launch_bounds__(256, 3) void pair_kernel(
    const float* __restrict__ gamma, const float* __restrict__ beta,
    const float* __restrict__ W2, const float* __restrict__ b2,
    float* __restrict__ out)
{
    __shared__ float sl[TI][DD];
    __shared__ float sr[TI][DD];
    __shared__ ull spg[8][32];    // packed gamma  (d = 64k + 2*lane)
    __shared__ ull spb[8][32];    // packed beta
    __shared__ ull spw[8][32];    // packed 0.5*w
    __shared__ float sSl[TI], sQl[TI], sAl[TI];
    __shared__ float sSr[TI], sQr[TI], sBr[TI];
    __shared__ float sC[TI][TI];
    __shared__ float sK[2];

    // Decode linear block id -> upper-triangular tile (ti <= tj).
    int bid = blockIdx.x;
    int ti = (int)((2.0f * TT + 1.0f -
                    sqrtf((2.0f * TT + 1.0f) * (2.0f * TT + 1.0f) - 8.0f * (float)bid)) * 0.5f);
    if (ti < 0) ti = 0;
    if (ti > TT - 1) ti = TT - 1;
    while (ti > 0 && (ti * TT - ((ti * (ti - 1)) >> 1)) > bid) ti--;
    while (((ti + 1) * TT - (((ti + 1) * ti) >> 1)) <= bid) ti++;
    const int tj = ti + bid - (ti * TT - ((ti * (ti - 1)) >> 1));

    const int t = threadIdx.x;
    const int lane = t & 31;
    const int w = t >> 5;

    const float* L = g_LR;
    const float* R = g_LR + NN * DD;

    // Stage rows.
#pragma unroll
    for (int c = 0; c < 4; c++) {
        int idx = c * 256 + t;
        int r = idx >> 7;
        int col = (idx & 127) << 2;
        *(float4*)&sl[r][col] = *(const float4*)&L[(ti * TI + r) * DD + col];
        *(float4*)&sr[r][col] = *(const float4*)&R[(tj * TI + r) * DD + col];
    }
    // Stage params (one shot, all 256 threads).
    {
        int k = t >> 5, ln = t & 31;
        int d = (k << 6) + (ln << 1);
        float2 gv = *(const float2*)&gamma[d];
        float2 bv = *(const float2*)&beta[d];
        float2 wv = *(const float2*)&W2[d];
        spg[k][ln] = pk(gv.x, gv.y);
        spb[k][ln] = pk(bv.x, bv.y);
        spw[k][ln] = pk(0.5f * wv.x, 0.5f * wv.y);
    }
    // Stage stats + C tile.
    if (t < 8)              sSl[t] = g_S[ti * TI + t];
    else if (t < 16)        sQl[t - 8]  = g_Q[ti * TI + t - 8];
    else if (t < 24)        sAl[t - 16] = g_A[ti * TI + t - 16];
    else if (t < 32)        sSr[t - 24] = g_S[NN + tj * TI + t - 24];
    else if (t < 40)        sQr[t - 32] = g_Q[NN + tj * TI + t - 32];
    else if (t < 48)        sBr[t - 40] = g_A[NN + tj * TI + t - 40];
    else if (t < 112) {
        int li = t - 48;
        sC[li >> 3][li & 7] = g_C[(ti * TI + (li >> 3)) * NN + tj * TI + (li & 7)];
    }
    else if (t == 112)      sK[0] = g_K[0];
    else if (t == 113)      sK[1] = g_K[1];

    const ull C1 = pkdup(0.0356774081f);
    const ull C0 = pkdup(0.7978845608f);

    __syncthreads();

    const int i = ti * TI + w;
    const float Sl = sSl[w], Ql = sQl[w], Al = sAl[w];
    const float K1 = sK[0], K2 = sK[1];

    // Prologue: per-jj LN stats + closed-form linear part.
    ull rstd2[TI], accJ2[TI];
    float ccs[TI];
#pragma unroll
    for (int jj = 0; jj < TI; jj++) {
        float sum = Sl + sSr[jj];
        float ssq = Ql + sQr[jj] + 2.0f * sC[w][jj];
        float mu  = sum * (1.0f / DD);
        float var = fmaf(-mu, mu, ssq * (1.0f / DD));
        float rstd = rsqrtf(var + LN_EPS);
        float cc = -mu * rstd;
        float lin = 0.5f * fmaf(rstd, Al + sBr[jj], fmaf(cc, K1, K2));
        rstd2[jj] = pkdup(rstd);
        ccs[jj] = cc;
        accJ2[jj] = pkdup(lin * (1.0f / 64.0f));  // sums to lin over 64 slots
    }

    // Main: k outer (params amortized over 8 pairs), jj inner.
#pragma unroll
    for (int k = 0; k < 8; k++) {
        const int off = (k << 6) + (lane << 1);
        ull lk = *(const ull*)&sl[w][off];
        ull gk = spg[k][lane];
        ull bk = spb[k][lane];
        ull wk = spw[k][lane];
#pragma unroll
        for (int jj = 0; jj < TI; jj++) {
            ull r2 = *(const ull*)&sr[jj][off];
            ull v = add2(lk, r2);
            ull cc2 = pkdup(ccs[jj]);
            ull x = fma2(v, rstd2[jj], cc2);
            x = fma2(x, gk, bk);
            ull x2 = mul2(x, x);
            ull p = fma2(x2, C1, C0);
            ull u = mul2(x, p);
            float ulo, uhi;
            upk(u, ulo, uhi);
            ull th = pk(tanh_approx(ulo), tanh_approx(uhi));
            ull xw = mul2(x, wk);
            accJ2[jj] = fma2(xw, th, accJ2[jj]);
        }
    }

    // Epilogue: 8 independent shuffle trees + sigmoid + mirrored store.
#pragma unroll
    for (int jj = 0; jj < TI; jj++) {
        float lo, hi;
        upk(accJ2[jj], lo, hi);
        float vsum = lo + hi;
#pragma unroll
        for (int o = 16; o > 0; o >>= 1)
            vsum += __shfl_xor_sync(0xffffffffu, vsum, o);
        int j = tj * TI + jj;
        float zv = vsum + b2[0];
        float e = __expf(-zv);
        float sig = __fdividef(1.0f, 1.0f + e);
        if (lane == jj && i <= j) {
            out[i * NN + j] = sig;
            out[j * NN + i] = sig;
        }
    }
}

// ---------------------------------------------------------------------------
extern "C" void kernel_launch(void* const* d_in, const int* in_sizes, int n_in,
                              void* d_out, int out_size)
{
    const float* E     = (const float*)d_in[0];
    const float* W1    = (const float*)d_in[1];
    const float* b1    = (const float*)d_in[2];
    const float* gamma = (const float*)d_in[3];
    const float* beta  = (const float*)d_in[4];
    const float* W2    = (const float*)d_in[5];
    const float* b2    = (const float*)d_in[6];
    float* out = (float*)d_out;

    dim3 ggrid(NN / 64, NN / 64, 2);
    gemm_tc<<<ggrid, 128>>>(E, W1, b1);

    rowstats_kernel<<<257, 128>>>(gamma, beta, W2);

    cross_tc<<<36, 128>>>();

    const int nblocks = TT * (TT + 1) / 2;   // 2080
    pair_kernel<<<nblocks, 256>>>(gamma, beta, W2, b2, out);
}